// round 1
// baseline (speedup 1.0000x reference)
#include <cuda_runtime.h>
#include <cuda_bf16.h>
#include <math.h>

#define Gn   256      // graphs
#define Nn   512      // nodes per graph
#define En   16384    // edges per graph
#define Hh   256      // hidden
#define FIN  4
#define TASKS 512     // 256 home + 256 away

// ---------------- scratch (device globals; no allocation) ----------------
__device__ float g_X[2][(size_t)TASKS * Nn * Hh];   // ping-pong: [0]=H features, [1]=GEMM out
__device__ float g_deg[TASKS * Nn];
__device__ float g_dinv[TASKS * Nn];
__device__ float g_selfnorm[TASKS * Nn];
__device__ int   g_cnt[TASKS * Nn];
__device__ int   g_cnt2[TASKS * Nn];
__device__ int   g_rowptr[TASKS * (Nn + 1)];
__device__ int   g_col[(size_t)TASKS * En];
__device__ float g_val[(size_t)TASKS * En];
__device__ float g_pool[TASKS * Hh];

// ---------------- prep: degree / CSR build ----------------
__global__ void prep_init() {
    int i = blockIdx.x * Nn + threadIdx.x;
    g_deg[i] = 1.0f;      // self-loop weight
    g_cnt[i] = 0;
    g_cnt2[i] = 0;
}

__global__ void prep_count(const int* __restrict__ hei, const int* __restrict__ aei,
                           const float* __restrict__ hew, const float* __restrict__ aew) {
    int task = blockIdx.x;
    int e = blockIdx.y * 256 + threadIdx.x;
    const int*   ei = (task < Gn) ? hei + (size_t)task * 2 * En : aei + (size_t)(task - Gn) * 2 * En;
    const float* ew = (task < Gn) ? hew + (size_t)task * En     : aew + (size_t)(task - Gn) * En;
    int t = ei[En + e];
    float w = ew[e];
    atomicAdd(&g_deg[task * Nn + t], w);
    atomicAdd(&g_cnt[task * Nn + t], 1);
}

__global__ void prep_scan() {
    __shared__ int s[Nn];
    int task = blockIdx.x, t = threadIdx.x;
    s[t] = g_cnt[task * Nn + t];
    __syncthreads();
    for (int off = 1; off < Nn; off <<= 1) {
        int v = (t >= off) ? s[t - off] : 0;
        __syncthreads();
        s[t] += v;
        __syncthreads();
    }
    g_rowptr[task * (Nn + 1) + t + 1] = s[t];
    if (t == 0) g_rowptr[task * (Nn + 1)] = 0;
    float d  = g_deg[task * Nn + t];
    float di = rsqrtf(d);
    g_dinv[task * Nn + t] = di;
    g_selfnorm[task * Nn + t] = di * di;
}

__global__ void prep_scatter(const int* __restrict__ hei, const int* __restrict__ aei,
                             const float* __restrict__ hew, const float* __restrict__ aew) {
    int task = blockIdx.x;
    int e = blockIdx.y * 256 + threadIdx.x;
    const int*   ei = (task < Gn) ? hei + (size_t)task * 2 * En : aei + (size_t)(task - Gn) * 2 * En;
    const float* ew = (task < Gn) ? hew + (size_t)task * En     : aew + (size_t)(task - Gn) * En;
    int s = ei[e];
    int t = ei[En + e];
    float w = ew[e];
    float norm = g_dinv[task * Nn + s] * w * g_dinv[task * Nn + t];
    int pos = g_rowptr[task * (Nn + 1) + t] + atomicAdd(&g_cnt2[task * Nn + t], 1);
    g_col[(size_t)task * En + pos] = s;
    g_val[(size_t)task * En + pos] = norm;
}

// ---------------- layer 0 GEMM: T = X[512,4] @ W0[4,256] ----------------
__global__ void gemm0(const float* __restrict__ hx, const float* __restrict__ ax,
                      const float* __restrict__ W0) {
    int task = blockIdx.x;
    int n0 = blockIdx.y * 8;
    int h = threadIdx.x;
    const float* x = (task < Gn) ? hx + (size_t)task * Nn * FIN
                                 : ax + (size_t)(task - Gn) * Nn * FIN;
    float w0 = W0[h], w1 = W0[Hh + h], w2 = W0[2 * Hh + h], w3 = W0[3 * Hh + h];
    float* T = &g_X[1][(size_t)task * Nn * Hh];
#pragma unroll
    for (int i = 0; i < 8; i++) {
        int n = n0 + i;
        float4 xv = *(const float4*)(x + n * 4);
        T[n * Hh + h] = xv.x * w0 + xv.y * w1 + xv.z * w2 + xv.w * w3;
    }
}

// ---------------- main GEMM: T = H[512,256] @ W[256,256] (per task) ----------------
// 64x64 tile, BK=16, 256 threads, 4x4 microtile.
__global__ __launch_bounds__(256) void gemm_hh(const float* __restrict__ B) {
    int task = blockIdx.z;
    const float* A = &g_X[0][(size_t)task * Nn * Hh];
    float*       C = &g_X[1][(size_t)task * Nn * Hh];
    int bm = blockIdx.y * 64, bn = blockIdx.x * 64;

    __shared__ float As[16][64];
    __shared__ float Bs[16][64];

    int tid = threadIdx.x;
    int tx = tid & 15, ty = tid >> 4;
    int lm = tid >> 2;          // 0..63 (A row within tile)
    int lk = (tid & 3) * 4;     // 0,4,8,12 (A k offset)
    int bkr = tid >> 4;         // 0..15 (B k row)
    int bn4 = (tid & 15) * 4;   // B col offset

    float acc[4][4];
#pragma unroll
    for (int i = 0; i < 4; i++)
#pragma unroll
        for (int j = 0; j < 4; j++) acc[i][j] = 0.f;

    for (int kb = 0; kb < Hh; kb += 16) {
        float4 av = *(const float4*)(A + (size_t)(bm + lm) * Hh + kb + lk);
        As[lk][lm] = av.x; As[lk + 1][lm] = av.y; As[lk + 2][lm] = av.z; As[lk + 3][lm] = av.w;
        *(float4*)&Bs[bkr][bn4] = *(const float4*)(B + (size_t)(kb + bkr) * Hh + bn + bn4);
        __syncthreads();
#pragma unroll
        for (int k = 0; k < 16; k++) {
            float4 a = *(float4*)&As[k][ty * 4];
            float4 b = *(float4*)&Bs[k][tx * 4];
            acc[0][0] += a.x * b.x; acc[0][1] += a.x * b.y; acc[0][2] += a.x * b.z; acc[0][3] += a.x * b.w;
            acc[1][0] += a.y * b.x; acc[1][1] += a.y * b.y; acc[1][2] += a.y * b.z; acc[1][3] += a.y * b.w;
            acc[2][0] += a.z * b.x; acc[2][1] += a.z * b.y; acc[2][2] += a.z * b.z; acc[2][3] += a.z * b.w;
            acc[3][0] += a.w * b.x; acc[3][1] += a.w * b.y; acc[3][2] += a.w * b.z; acc[3][3] += a.w * b.w;
        }
        __syncthreads();
    }
#pragma unroll
    for (int i = 0; i < 4; i++)
#pragma unroll
        for (int j = 0; j < 4; j++)
            C[(size_t)(bm + ty * 4 + i) * Hh + bn + tx * 4 + j] = acc[i][j];
}

// ---------------- aggregation: Hout = relu(A_norm @ T + b), smem-cached slice ----------------
// grid (4 channel-slices, TASKS), block 512 (16 warps), 128KB dyn smem.
__global__ __launch_bounds__(512) void aggregate(const float* __restrict__ bias) {
    extern __shared__ float sh[];   // [Nn][64]
    int task = blockIdx.y;
    int c0 = blockIdx.x * 64;
    const float* T = &g_X[1][(size_t)task * Nn * Hh];
    float*    Hout = &g_X[0][(size_t)task * Nn * Hh];

    // stage the [512 x 64] feature slice in smem (float4 coalesced)
    for (int i = threadIdx.x; i < Nn * 16; i += blockDim.x) {
        int n = i >> 4, q = i & 15;
        ((float4*)sh)[n * 16 + q] = *(const float4*)(T + (size_t)n * Hh + c0 + q * 4);
    }
    __syncthreads();

    int lane = threadIdx.x & 31, warp = threadIdx.x >> 5;
    float b0 = bias[c0 + lane], b1 = bias[c0 + 32 + lane];
    const int*   rp  = g_rowptr + task * (Nn + 1);
    const int*   col = g_col + (size_t)task * En;
    const float* val = g_val + (size_t)task * En;

    for (int t = warp; t < Nn; t += 16) {
        float a0 = b0, a1 = b1;
        int rs = rp[t], re = rp[t + 1];
        for (int e = rs; e < re; e += 32) {
            int idx = 0; float v = 0.f;
            if (e + lane < re) { idx = col[e + lane]; v = val[e + lane]; }
            int cnt = min(32, re - e);
            for (int j = 0; j < cnt; j++) {
                int   s  = __shfl_sync(0xffffffff, idx, j);
                float vv = __shfl_sync(0xffffffff, v, j);
                a0 += vv * sh[s * 64 + lane];
                a1 += vv * sh[s * 64 + 32 + lane];
            }
        }
        float sn = g_selfnorm[task * Nn + t];
        a0 += sn * sh[t * 64 + lane];
        a1 += sn * sh[t * 64 + 32 + lane];
        a0 = fmaxf(a0, 0.f); a1 = fmaxf(a1, 0.f);
        Hout[(size_t)t * Hh + c0 + lane]      = a0;
        Hout[(size_t)t * Hh + c0 + 32 + lane] = a1;
    }
}

// ---------------- mean pool over nodes ----------------
__global__ void poolk() {
    int task = blockIdx.x, c = threadIdx.x;
    const float* Hf = &g_X[0][(size_t)task * Nn * Hh];
    float s = 0.f;
    for (int n = 0; n < Nn; n++) s += Hf[(size_t)n * Hh + c];
    g_pool[task * Hh + c] = s * (1.0f / Nn);
}

// ---------------- FC head ----------------
__global__ void fck(const float* __restrict__ hfeat, const float* __restrict__ afeat,
                    const float* __restrict__ fcW, const float* __restrict__ fcb,
                    float* __restrict__ out) {
    int g = blockIdx.x;
    int c = threadIdx.x >> 5;   // 0..2
    int lane = threadIdx.x & 31;
    float acc = 0.f;
    for (int i = lane; i < 2 * (Hh + 6); i += 32) {
        float xv;
        if      (i < 256) xv = g_pool[g * Hh + i];
        else if (i < 262) xv = hfeat[g * 6 + (i - 256)];
        else if (i < 518) xv = g_pool[(Gn + g) * Hh + (i - 262)];
        else              xv = afeat[g * 6 + (i - 518)];
        acc += xv * fcW[i * 3 + c];
    }
#pragma unroll
    for (int o = 16; o; o >>= 1) acc += __shfl_down_sync(0xffffffff, acc, o);
    if (lane == 0) out[g * 3 + c] = acc + fcb[c];
}

// ---------------- launch ----------------
extern "C" void kernel_launch(void* const* d_in, const int* in_sizes, int n_in,
                              void* d_out, int out_size) {
    const float* home_x = (const float*)d_in[0];
    const float* away_x = (const float*)d_in[1];
    const int*   hei    = (const int*)d_in[2];
    const int*   aei    = (const int*)d_in[3];
    const float* hew    = (const float*)d_in[4];
    const float* aew    = (const float*)d_in[5];
    const float* hfeat  = (const float*)d_in[6];
    const float* afeat  = (const float*)d_in[7];
    const float* W0     = (const float*)d_in[8];
    const float* Wh     = (const float*)d_in[9];
    const float* bs     = (const float*)d_in[10];
    const float* fcW    = (const float*)d_in[11];
    const float* fcb    = (const float*)d_in[12];
    float* out = (float*)d_out;

    cudaFuncSetAttribute(aggregate, cudaFuncAttributeMaxDynamicSharedMemorySize, 131072);

    // build normalized adjacency CSR (once per call; shared by all 5 layers)
    prep_init<<<TASKS, Nn>>>();
    prep_count<<<dim3(TASKS, En / 256), 256>>>(hei, aei, hew, aew);
    prep_scan<<<TASKS, Nn>>>();
    prep_scatter<<<dim3(TASKS, En / 256), 256>>>(hei, aei, hew, aew);

    // layer 0
    gemm0<<<dim3(TASKS, Nn / 8), Hh>>>(home_x, away_x, W0);
    aggregate<<<dim3(4, TASKS), 512, 131072>>>(bs);

    // layers 1..4
    for (int l = 1; l < 5; l++) {
        gemm_hh<<<dim3(Hh / 64, Nn / 64, TASKS), 256>>>(Wh + (size_t)(l - 1) * Hh * Hh);
        aggregate<<<dim3(4, TASKS), 512, 131072>>>(bs + l * Hh);
    }

    // head
    poolk<<<TASKS, Hh>>>();
    fck<<<Gn, 96>>>(hfeat, afeat, fcW, fcb, out);
}

// round 3
// speedup vs baseline: 1.4447x; 1.4447x over previous
#include <cuda_runtime.h>
#include <cuda_bf16.h>
#include <math.h>
#include <stdint.h>

#define Gn   256      // graphs
#define Nn   512      // nodes per graph
#define En   16384    // edges per graph
#define Hh   256      // hidden
#define FIN  4
#define TASKS 512     // 256 home + 256 away

// ---------------- scratch (device globals; no allocation) ----------------
__device__ float g_X[2][(size_t)TASKS * Nn * Hh];   // ping-pong
__device__ float g_deg[TASKS * Nn];
__device__ float g_dinv[TASKS * Nn];
__device__ float g_selfnorm[TASKS * Nn];
__device__ int   g_cnt[TASKS * Nn];
__device__ int   g_cnt2[TASKS * Nn];
__device__ int   g_rowptr[TASKS * (Nn + 1)];
__device__ int   g_col[(size_t)TASKS * En];
__device__ float g_val[(size_t)TASKS * En];
__device__ float g_pool[TASKS * Hh];
__device__ float g_Wt[4 * Hh * Hh];   // tf32-rounded weights, [l][k][n]

__device__ __forceinline__ float totf32(float x) {
    uint32_t o;
    asm("cvt.rna.tf32.f32 %0, %1;" : "=r"(o) : "f"(x));
    return __uint_as_float(o);
}

__device__ __forceinline__ void mma_tf32(float* c, const uint32_t* a, const uint32_t* b) {
    asm volatile(
        "mma.sync.aligned.m16n8k8.row.col.f32.tf32.tf32.f32 "
        "{%0,%1,%2,%3}, {%4,%5,%6,%7}, {%8,%9}, {%0,%1,%2,%3};"
        : "+f"(c[0]), "+f"(c[1]), "+f"(c[2]), "+f"(c[3])
        : "r"(a[0]), "r"(a[1]), "r"(a[2]), "r"(a[3]), "r"(b[0]), "r"(b[1]));
}

// ---------------- prep: degree / CSR build ----------------
__global__ void prep_init() {
    int i = blockIdx.x * Nn + threadIdx.x;
    g_deg[i] = 1.0f;
    g_cnt[i] = 0;
    g_cnt2[i] = 0;
}

__global__ void prep_count(const int* __restrict__ hei, const int* __restrict__ aei,
                           const float* __restrict__ hew, const float* __restrict__ aew) {
    int task = blockIdx.x;
    int e = blockIdx.y * 256 + threadIdx.x;
    const int*   ei = (task < Gn) ? hei + (size_t)task * 2 * En : aei + (size_t)(task - Gn) * 2 * En;
    const float* ew = (task < Gn) ? hew + (size_t)task * En     : aew + (size_t)(task - Gn) * En;
    int t = ei[En + e];
    float w = ew[e];
    atomicAdd(&g_deg[task * Nn + t], w);
    atomicAdd(&g_cnt[task * Nn + t], 1);
}

__global__ void prep_scan() {
    __shared__ int s[Nn];
    int task = blockIdx.x, t = threadIdx.x;
    s[t] = g_cnt[task * Nn + t];
    __syncthreads();
    for (int off = 1; off < Nn; off <<= 1) {
        int v = (t >= off) ? s[t - off] : 0;
        __syncthreads();
        s[t] += v;
        __syncthreads();
    }
    g_rowptr[task * (Nn + 1) + t + 1] = s[t];
    if (t == 0) g_rowptr[task * (Nn + 1)] = 0;
    float d  = g_deg[task * Nn + t];
    float di = rsqrtf(d);
    g_dinv[task * Nn + t] = di;
    g_selfnorm[task * Nn + t] = di * di;
}

__global__ void prep_scatter(const int* __restrict__ hei, const int* __restrict__ aei,
                             const float* __restrict__ hew, const float* __restrict__ aew) {
    int task = blockIdx.x;
    int e = blockIdx.y * 256 + threadIdx.x;
    const int*   ei = (task < Gn) ? hei + (size_t)task * 2 * En : aei + (size_t)(task - Gn) * 2 * En;
    const float* ew = (task < Gn) ? hew + (size_t)task * En     : aew + (size_t)(task - Gn) * En;
    int s = ei[e];
    int t = ei[En + e];
    float w = ew[e];
    float norm = g_dinv[task * Nn + s] * w * g_dinv[task * Nn + t];
    int pos = g_rowptr[task * (Nn + 1) + t] + atomicAdd(&g_cnt2[task * Nn + t], 1);
    g_col[(size_t)task * En + pos] = s;
    g_val[(size_t)task * En + pos] = norm;
}

// ---------------- weight tf32 round (layout unchanged: [l][k][n]) ----------------
__global__ void wt_prep(const float* __restrict__ Wh) {
    size_t i = (size_t)blockIdx.x * 256 + threadIdx.x;
    g_Wt[i] = totf32(Wh[i]);
}

// ---------------- layer 0 GEMM: T = X[512,4] @ W0[4,256] ----------------
__global__ void gemm0(const float* __restrict__ hx, const float* __restrict__ ax,
                      const float* __restrict__ W0) {
    int task = blockIdx.x;
    int n0 = blockIdx.y * 8;
    int h = threadIdx.x;
    const float* x = (task < Gn) ? hx + (size_t)task * Nn * FIN
                                 : ax + (size_t)(task - Gn) * Nn * FIN;
    float w0 = W0[h], w1 = W0[Hh + h], w2 = W0[2 * Hh + h], w3 = W0[3 * Hh + h];
    float* T = &g_X[1][(size_t)task * Nn * Hh];
#pragma unroll
    for (int i = 0; i < 8; i++) {
        int n = n0 + i;
        float4 xv = *(const float4*)(x + n * 4);
        T[n * Hh + h] = xv.x * w0 + xv.y * w1 + xv.z * w2 + xv.w * w3;
    }
}

// ---------------- tf32 mma.sync GEMM: C[128,128] = A[128,256] @ W[256,128] ----------------
// grid (2 N-blocks, 4 M-blocks, 512 tasks), 256 threads = 8 warps of 32x64.
#define AS_S 36
#define BS_S 132

__global__ __launch_bounds__(256) void gemm_mma(int layer) {
    __shared__ float As[128 * AS_S];   // [m][k], pad 36
    __shared__ float Bs[32 * BS_S];    // [k][n], pad 132

    const int task = blockIdx.z;
    const int bm = blockIdx.y * 128;
    const int bn = blockIdx.x * 128;
    const float* A  = &g_X[0][(size_t)task * Nn * Hh + (size_t)bm * Hh];
    float*       C  = &g_X[1][(size_t)task * Nn * Hh + (size_t)bm * Hh + bn];
    const float* W  = g_Wt + (size_t)layer * Hh * Hh + bn;

    const int tid  = threadIdx.x;
    const int lane = tid & 31;
    const int wid  = tid >> 5;
    const int m_off = (wid & 3) * 32;
    const int n_off = (wid >> 2) * 64;
    const int gid = lane >> 2;      // 0..7
    const int tig = lane & 3;       // 0..3

    float acc[2][8][4];
#pragma unroll
    for (int mi = 0; mi < 2; mi++)
#pragma unroll
        for (int ni = 0; ni < 8; ni++)
#pragma unroll
            for (int q = 0; q < 4; q++) acc[mi][ni][q] = 0.f;

    for (int kb = 0; kb < Hh; kb += 32) {
        // load A chunk: 128 rows x 8 float4
#pragma unroll
        for (int it = 0; it < 4; it++) {
            int i = tid + it * 256;
            int r = i >> 3, q = i & 7;
            float4 v = *(const float4*)(A + (size_t)r * Hh + kb + q * 4);
            v.x = totf32(v.x); v.y = totf32(v.y); v.z = totf32(v.z); v.w = totf32(v.w);
            *(float4*)&As[r * AS_S + q * 4] = v;
        }
        // load B chunk: 32 rows x 32 float4 (already tf32-rounded)
#pragma unroll
        for (int it = 0; it < 4; it++) {
            int i = tid + it * 256;
            int r = i >> 5, q = i & 31;
            *(float4*)&Bs[r * BS_S + q * 4] = *(const float4*)(W + (size_t)(kb + r) * Hh + q * 4);
        }
        __syncthreads();

#pragma unroll
        for (int k = 0; k < 32; k += 8) {
            uint32_t af[2][4], bf[8][2];
#pragma unroll
            for (int mi = 0; mi < 2; mi++) {
                int m = m_off + mi * 16 + gid;
                af[mi][0] = __float_as_uint(As[m * AS_S + k + tig]);
                af[mi][1] = __float_as_uint(As[(m + 8) * AS_S + k + tig]);
                af[mi][2] = __float_as_uint(As[m * AS_S + k + tig + 4]);
                af[mi][3] = __float_as_uint(As[(m + 8) * AS_S + k + tig + 4]);
            }
#pragma unroll
            for (int ni = 0; ni < 8; ni++) {
                int n = n_off + ni * 8 + gid;
                bf[ni][0] = __float_as_uint(Bs[(k + tig) * BS_S + n]);
                bf[ni][1] = __float_as_uint(Bs[(k + tig + 4) * BS_S + n]);
            }
#pragma unroll
            for (int mi = 0; mi < 2; mi++)
#pragma unroll
                for (int ni = 0; ni < 8; ni++)
                    mma_tf32(acc[mi][ni], af[mi], bf[ni]);
        }
        __syncthreads();
    }

    // epilogue: c0/c1 at (row, 2*tig), c2/c3 at (row+8, 2*tig)
#pragma unroll
    for (int mi = 0; mi < 2; mi++) {
        int r0 = m_off + mi * 16 + gid;
#pragma unroll
        for (int ni = 0; ni < 8; ni++) {
            int cl = n_off + ni * 8 + tig * 2;
            *(float2*)(C + (size_t)r0 * Hh + cl)       = make_float2(acc[mi][ni][0], acc[mi][ni][1]);
            *(float2*)(C + (size_t)(r0 + 8) * Hh + cl) = make_float2(acc[mi][ni][2], acc[mi][ni][3]);
        }
    }
}

// ---------------- aggregation: Hout = relu(A_norm @ T + b), smem-cached slice ----------------
__global__ __launch_bounds__(512) void aggregate(const float* __restrict__ bias) {
    extern __shared__ float sh[];   // [Nn][64]
    int task = blockIdx.y;
    int c0 = blockIdx.x * 64;
    const float* T = &g_X[1][(size_t)task * Nn * Hh];
    float*    Hout = &g_X[0][(size_t)task * Nn * Hh];

    for (int i = threadIdx.x; i < Nn * 16; i += blockDim.x) {
        int n = i >> 4, q = i & 15;
        ((float4*)sh)[n * 16 + q] = *(const float4*)(T + (size_t)n * Hh + c0 + q * 4);
    }
    __syncthreads();

    int lane = threadIdx.x & 31, warp = threadIdx.x >> 5;
    float b0 = bias[c0 + lane], b1 = bias[c0 + 32 + lane];
    const int*   rp  = g_rowptr + task * (Nn + 1);
    const int*   col = g_col + (size_t)task * En;
    const float* val = g_val + (size_t)task * En;

    for (int t = warp; t < Nn; t += 16) {
        float a0 = b0, a1 = b1;
        int rs = rp[t], re = rp[t + 1];
        for (int e = rs; e < re; e += 32) {
            int idx = 0; float v = 0.f;
            if (e + lane < re) { idx = col[e + lane]; v = val[e + lane]; }
            int cnt = min(32, re - e);
            for (int j = 0; j < cnt; j++) {
                int   s  = __shfl_sync(0xffffffff, idx, j);
                float vv = __shfl_sync(0xffffffff, v, j);
                a0 += vv * sh[s * 64 + lane];
                a1 += vv * sh[s * 64 + 32 + lane];
            }
        }
        float sn = g_selfnorm[task * Nn + t];
        a0 += sn * sh[t * 64 + lane];
        a1 += sn * sh[t * 64 + 32 + lane];
        a0 = fmaxf(a0, 0.f); a1 = fmaxf(a1, 0.f);
        Hout[(size_t)t * Hh + c0 + lane]      = a0;
        Hout[(size_t)t * Hh + c0 + 32 + lane] = a1;
    }
}

// ---------------- mean pool over nodes ----------------
__global__ void poolk() {
    int task = blockIdx.x, c = threadIdx.x;
    const float* Hf = &g_X[0][(size_t)task * Nn * Hh];
    float s = 0.f;
    for (int n = 0; n < Nn; n++) s += Hf[(size_t)n * Hh + c];
    g_pool[task * Hh + c] = s * (1.0f / Nn);
}

// ---------------- FC head ----------------
__global__ void fck(const float* __restrict__ hfeat, const float* __restrict__ afeat,
                    const float* __restrict__ fcW, const float* __restrict__ fcb,
                    float* __restrict__ out) {
    int g = blockIdx.x;
    int c = threadIdx.x >> 5;
    int lane = threadIdx.x & 31;
    float acc = 0.f;
    for (int i = lane; i < 2 * (Hh + 6); i += 32) {
        float xv;
        if      (i < 256) xv = g_pool[g * Hh + i];
        else if (i < 262) xv = hfeat[g * 6 + (i - 256)];
        else if (i < 518) xv = g_pool[(Gn + g) * Hh + (i - 262)];
        else              xv = afeat[g * 6 + (i - 518)];
        acc += xv * fcW[i * 3 + c];
    }
#pragma unroll
    for (int o = 16; o; o >>= 1) acc += __shfl_down_sync(0xffffffff, acc, o);
    if (lane == 0) out[g * 3 + c] = acc + fcb[c];
}

// ---------------- launch ----------------
extern "C" void kernel_launch(void* const* d_in, const int* in_sizes, int n_in,
                              void* d_out, int out_size) {
    const float* home_x = (const float*)d_in[0];
    const float* away_x = (const float*)d_in[1];
    const int*   hei    = (const int*)d_in[2];
    const int*   aei    = (const int*)d_in[3];
    const float* hew    = (const float*)d_in[4];
    const float* aew    = (const float*)d_in[5];
    const float* hfeat  = (const float*)d_in[6];
    const float* afeat  = (const float*)d_in[7];
    const float* W0     = (const float*)d_in[8];
    const float* Wh     = (const float*)d_in[9];
    const float* bs     = (const float*)d_in[10];
    const float* fcW    = (const float*)d_in[11];
    const float* fcb    = (const float*)d_in[12];
    float* out = (float*)d_out;

    cudaFuncSetAttribute(aggregate, cudaFuncAttributeMaxDynamicSharedMemorySize, 131072);

    // build normalized adjacency CSR + tf32 weights (shared by all layers)
    wt_prep<<<4 * Hh * Hh / 256, 256>>>(Wh);
    prep_init<<<TASKS, Nn>>>();
    prep_count<<<dim3(TASKS, En / 256), 256>>>(hei, aei, hew, aew);
    prep_scan<<<TASKS, Nn>>>();
    prep_scatter<<<dim3(TASKS, En / 256), 256>>>(hei, aei, hew, aew);

    // layer 0
    gemm0<<<dim3(TASKS, Nn / 8), Hh>>>(home_x, away_x, W0);
    aggregate<<<dim3(4, TASKS), 512, 131072>>>(bs);

    // layers 1..4 on tensor cores (mma.sync tf32)
    for (int l = 1; l < 5; l++) {
        gemm_mma<<<dim3(2, 4, TASKS), 256>>>(l - 1);
        aggregate<<<dim3(4, TASKS), 512, 131072>>>(bs + l * Hh);
    }

    // head
    poolk<<<TASKS, Hh>>>();
    fck<<<Gn, 96>>>(hfeat, afeat, fcW, fcb, out);
}